// round 8
// baseline (speedup 1.0000x reference)
#include <cuda_runtime.h>
#include <math.h>

// out[b][i] = cos(theta_i) * Z_i / T
//   T   = sum_k x_k^2 (NaN-scrubbed),  Z_i = sum_k sign_i(k) x_k^2,
//   sign_i(k) = +1 if bit (3-i) of k == 0  (wire 0 = MSB).
//
// Quad-cooperative, warp tile = 64 samples: 8 front-batched LDG.128, each
// warp-contiguous (512B) -> minimal L1 wavefronts, MLP_p1=8.
// Element k = (lane&3)*4 + comp:
//   k bit3 = lane bit1 (wire 0), k bit2 = lane bit0 (wire 1),
//   k bits 1:0 = component bits (wires 2,3).
// 4 shuffles/group (see per-line comments); lane j emits wire j^2 and
// writes out[lane^2] -> 128B coalesced store per group.
// NaN scrub: fmaxf(x*x,0) == x*x for non-NaN (>=0), == 0 for NaN.
__global__ void __launch_bounds__(256) quantum_z_kernel(
    const float4* __restrict__ x, float* __restrict__ out,
    const float* __restrict__ qw, int B)
{
    __shared__ float sc[4];
    if (threadIdx.x < 4) sc[threadIdx.x] = cosf(qw[threadIdx.x]);
    __syncthreads();

    int gtid   = blockIdx.x * blockDim.x + threadIdx.x;
    int warpId = gtid >> 5;
    int lane   = threadIdx.x & 31;

    if (warpId * 64 >= B) return;   // warp tile = 64 samples (B % 64 == 0)

    const float4* base = x + (size_t)warpId * 256;   // 64 samples * 4 float4
    float* obase = out + (size_t)warpId * 256;

    // 8 front-batched fully-coalesced loads (MLP=8).
    float4 v[8];
    #pragma unroll
    for (int g = 0; g < 8; ++g) v[g] = __ldcs(&base[g * 32 + lane]);

    int  j   = lane & 3;
    float c  = sc[j ^ 2];          // lane j emits wire j^2
    bool odd = (lane & 1);
    bool is1 = (j == 1), is2 = (j == 2), is3 = (j == 3);

    #pragma unroll
    for (int g = 0; g < 8; ++g) {
        float s0 = fmaxf(v[g].x * v[g].x, 0.0f);
        float s1 = fmaxf(v[g].y * v[g].y, 0.0f);
        float s2 = fmaxf(v[g].z * v[g].z, 0.0f);
        float s3 = fmaxf(v[g].w * v[g].w, 0.0f);

        float p01 = s0 + s1, p23 = s2 + s3;
        float t     = p01 + p23;
        float z2loc = p01 - p23;               // wire 2 (comp bit1)
        float z3loc = (s0 - s1) + (s2 - s3);   // wire 3 (comp bit0)

        // Stage 1 over lane bit0: pair-sum AND wire-1 partial from one shfl
        float sh1 = __shfl_xor_sync(0xFFFFFFFFu, t, 1);
        float tp  = t + sh1;                   // pair sum
        float z1p = sh1 - t;                   // wire-1 partial (odd lanes)

        float w   = odd ? z2loc : z3loc;       // payload swap
        float sh4 = __shfl_xor_sync(0xFFFFFFFFu, w, 1);
        float m   = (odd ? z3loc : z2loc) + sh4;   // even: Z2-pair, odd: Z3-pair

        // Stage 2 over lane bit1
        float sh2 = __shfl_xor_sync(0xFFFFFFFFu, tp, 2);
        float T   = tp + sh2;
        // lane j=2 (bit1=1): Z0 = sh2 - tp

        float send  = is1 ? z1p : m;           // j1->z1p (for j3); others->m
        float recv2 = __shfl_xor_sync(0xFFFFFFFFu, send, 2);
        // j0: m+recv2 = Z2;  j1: m+recv2 = Z3;  j3: z1p+recv2 = Z1
        float Zacc = (is3 ? z1p : m) + recv2;
        float Z    = is2 ? (sh2 - tp) : Zacc;

        obase[g * 32 + (lane ^ 2)] = c * __fdividef(Z, T);
    }
}

extern "C" void kernel_launch(void* const* d_in, const int* in_sizes, int n_in,
                              void* d_out, int out_size) {
    const float* x  = (const float*)d_in[0];
    const float* qw = (const float*)d_in[1];
    float* out = (float*)d_out;

    int B = in_sizes[0] / 16;                 // 2^21 samples
    // 64 samples/warp, 8 warps/block -> 512 samples per block.
    int blocks = (B + 511) / 512;

    quantum_z_kernel<<<blocks, 256>>>(
        (const float4*)x, out, qw, B);
}

// round 9
// speedup vs baseline: 1.0643x; 1.0643x over previous
#include <cuda_runtime.h>
#include <math.h>

// out[b][i] = cos(theta_i) * Z_i / T
//   T   = sum_k x_k^2 (NaN-scrubbed),  Z_i = sum_k sign_i(k) x_k^2,
//   sign_i(k) = +1 if bit (3-i) of k == 0  (wire 0 = MSB).
//
// Quad-cooperative, warp tile = 32 samples: 4 front-batched LDG.128, each
// warp-contiguous (512B). Element k = (lane&3)*4 + comp:
//   k bit3 = lane bit1 (wire 0), k bit2 = lane bit0 (wire 1),
//   k bits 1:0 = component bits (wires 2,3).
//
// 4 shuffles/group:
//  S1a: shfl(t,1)  -> pair-sum tp AND z1p = sh1 - t
//  S1b: payload swap (even sends z3loc, odd z2loc) -> m = Z2/Z3 pair
//  S2a: shfl(tp,2) -> T everywhere; Z0 = sh2 - tp free for lane j=2
//  S2b: payload swap (j==1 sends z1p, else m) -> Z2 (j0), Z3 (j1), Z1 (j3)
// Lane j emits wire j^2, writes out[lane^2] (128B coalesced store).
// NaN scrub: fmaxf(x*x,0) == x*x for non-NaN (>=0), == 0 for NaN.
// cos via __cosf (1 MUFU/thread; |err| ~1e-6 << 1e-3 tolerance) — no
// smem, no __syncthreads, no block prologue.
__global__ void __launch_bounds__(256) quantum_z_kernel(
    const float4* __restrict__ x, float* __restrict__ out,
    const float* __restrict__ qw, int B)
{
    int gtid   = blockIdx.x * blockDim.x + threadIdx.x;
    int warpId = gtid >> 5;
    int lane   = threadIdx.x & 31;

    if (warpId * 32 >= B) return;   // warp tile = 32 samples (B % 32 == 0)

    const float4* base = x + (size_t)warpId * 128;   // 32 samples * 4 float4
    float* obase = out + (size_t)warpId * 128;

    float4 v[4];
    #pragma unroll
    for (int g = 0; g < 4; ++g) v[g] = __ldcs(&base[g * 32 + lane]);

    int  j   = lane & 3;
    float c  = __cosf(__ldg(&qw[j ^ 2]));   // lane j emits wire j^2
    bool odd = (lane & 1);
    bool is1 = (j == 1), is2 = (j == 2), is3 = (j == 3);

    #pragma unroll
    for (int g = 0; g < 4; ++g) {
        float s0 = fmaxf(v[g].x * v[g].x, 0.0f);
        float s1 = fmaxf(v[g].y * v[g].y, 0.0f);
        float s2 = fmaxf(v[g].z * v[g].z, 0.0f);
        float s3 = fmaxf(v[g].w * v[g].w, 0.0f);

        float p01 = s0 + s1, p23 = s2 + s3;
        float t     = p01 + p23;
        float z2loc = p01 - p23;               // wire 2 (comp bit1)
        float z3loc = (s0 - s1) + (s2 - s3);   // wire 3 (comp bit0)

        // Stage 1 over lane bit0
        float sh1 = __shfl_xor_sync(0xFFFFFFFFu, t, 1);
        float tp  = t + sh1;                   // pair sum
        float z1p = sh1 - t;                   // wire-1 partial (odd lanes)

        float w   = odd ? z2loc : z3loc;       // payload swap
        float sh4 = __shfl_xor_sync(0xFFFFFFFFu, w, 1);
        float m   = (odd ? z3loc : z2loc) + sh4;   // even: Z2-pair, odd: Z3-pair

        // Stage 2 over lane bit1
        float sh2 = __shfl_xor_sync(0xFFFFFFFFu, tp, 2);
        float T   = tp + sh2;
        // lane j=2 (bit1=1): Z0 = sh2 - tp

        float send  = is1 ? z1p : m;           // j1->z1p (for j3); others->m
        float recv2 = __shfl_xor_sync(0xFFFFFFFFu, send, 2);
        // j0: m+recv2 = Z2;  j1: m+recv2 = Z3;  j3: z1p+recv2 = Z1
        float Zacc = (is3 ? z1p : m) + recv2;
        float Z    = is2 ? (sh2 - tp) : Zacc;

        obase[g * 32 + (lane ^ 2)] = c * __fdividef(Z, T);
    }
}

extern "C" void kernel_launch(void* const* d_in, const int* in_sizes, int n_in,
                              void* d_out, int out_size) {
    const float* x  = (const float*)d_in[0];
    const float* qw = (const float*)d_in[1];
    float* out = (float*)d_out;

    int B = in_sizes[0] / 16;                 // 2^21 samples
    int blocks = (B + 255) / 256;             // 256 samples per block

    quantum_z_kernel<<<blocks, 256>>>(
        (const float4*)x, out, qw, B);
}

// round 10
// speedup vs baseline: 1.1635x; 1.0932x over previous
#include <cuda_runtime.h>
#include <math.h>

// out[b][i] = cos(theta_i) * Z_i / T
//   T   = sum_k x_k^2 (NaN-scrubbed),  Z_i = sum_k sign_i(k) x_k^2,
//   sign_i(k) = +1 if bit (3-i) of k == 0  (wire 0 = MSB).
//
// Quad-cooperative, warp tile = 32 samples: 4 front-batched LDG.128, each
// warp-contiguous (512B). Element k = (lane&3)*4 + comp:
//   k bit3 = lane bit1 (wire 0), k bit2 = lane bit0 (wire 1),
//   k bits 1:0 = component bits (wires 2,3).
//
// 4 shuffles/group:
//  S1a: shfl(t,1)  -> pair-sum tp AND z1p = sh1 - t
//  S1b: payload swap (even sends z3loc, odd z2loc) -> m = Z2/Z3 pair
//  S2a: shfl(tp,2) -> T everywhere; Z0 = sh2 - tp free for lane j=2
//  S2b: payload swap (j==1 sends z1p, else m) -> Z2 (j0), Z3 (j1), Z1 (j3)
// Lane j emits wire j^2, writes out[lane^2] (128B coalesced store).
// NaN scrub: fmaxf(x*x,0) == x*x for non-NaN (>=0), == 0 for NaN.
// cos via __cosf (1 MUFU/thread; |err| ~1e-6 << 1e-3 tolerance).
// 512-thread blocks: half the CTA count of R9, same warp occupancy.
__global__ void __launch_bounds__(512) quantum_z_kernel(
    const float4* __restrict__ x, float* __restrict__ out,
    const float* __restrict__ qw, int B)
{
    int gtid   = blockIdx.x * blockDim.x + threadIdx.x;
    int warpId = gtid >> 5;
    int lane   = threadIdx.x & 31;

    if (warpId * 32 >= B) return;   // warp tile = 32 samples (B % 32 == 0)

    const float4* base = x + (size_t)warpId * 128;        // 32 samples * 4 float4
    float* obase = out + (size_t)warpId * 128 + (lane ^ 2);

    float4 v[4];
    #pragma unroll
    for (int g = 0; g < 4; ++g) v[g] = __ldcs(&base[g * 32 + lane]);

    int  j   = lane & 3;
    float c  = __cosf(qw[j ^ 2]);   // lane j emits wire j^2
    bool odd = (lane & 1);
    bool is1 = (j == 1), is2 = (j == 2), is3 = (j == 3);

    #pragma unroll
    for (int g = 0; g < 4; ++g) {
        float s0 = fmaxf(v[g].x * v[g].x, 0.0f);
        float s1 = fmaxf(v[g].y * v[g].y, 0.0f);
        float s2 = fmaxf(v[g].z * v[g].z, 0.0f);
        float s3 = fmaxf(v[g].w * v[g].w, 0.0f);

        float p01 = s0 + s1, p23 = s2 + s3;
        float t     = p01 + p23;
        float z2loc = p01 - p23;               // wire 2 (comp bit1)
        float z3loc = (s0 - s1) + (s2 - s3);   // wire 3 (comp bit0)

        // Stage 1 over lane bit0
        float sh1 = __shfl_xor_sync(0xFFFFFFFFu, t, 1);
        float tp  = t + sh1;                   // pair sum
        float z1p = sh1 - t;                   // wire-1 partial (odd lanes)

        float w   = odd ? z2loc : z3loc;       // payload swap
        float sh4 = __shfl_xor_sync(0xFFFFFFFFu, w, 1);
        float m   = (odd ? z3loc : z2loc) + sh4;   // even: Z2-pair, odd: Z3-pair

        // Stage 2 over lane bit1
        float sh2 = __shfl_xor_sync(0xFFFFFFFFu, tp, 2);
        float T   = tp + sh2;
        // lane j=2 (bit1=1): Z0 = sh2 - tp

        float send  = is1 ? z1p : m;           // j1->z1p (for j3); others->m
        float recv2 = __shfl_xor_sync(0xFFFFFFFFu, send, 2);
        // j0: m+recv2 = Z2;  j1: m+recv2 = Z3;  j3: z1p+recv2 = Z1
        float Zacc = (is3 ? z1p : m) + recv2;
        float Z    = is2 ? (sh2 - tp) : Zacc;

        obase[g * 32] = c * __fdividef(Z, T);
    }
}

extern "C" void kernel_launch(void* const* d_in, const int* in_sizes, int n_in,
                              void* d_out, int out_size) {
    const float* x  = (const float*)d_in[0];
    const float* qw = (const float*)d_in[1];
    float* out = (float*)d_out;

    int B = in_sizes[0] / 16;                 // 2^21 samples
    // 32 samples/warp, 16 warps/block -> 512 samples per block.
    int blocks = (B + 511) / 512;

    quantum_z_kernel<<<blocks, 512>>>(
        (const float4*)x, out, qw, B);
}